// round 1
// baseline (speedup 1.0000x reference)
#include <cuda_runtime.h>
#include <cuda_bf16.h>

#define NN 10000
#define EE 320000
#define CC 256
#define LL 3
#define DD 20
#define GAMMA 0.705078125f   // 0.5/(2*interval)^2, interval = 8/19
#define DICT_STEP (8.0f/19.0f)

// ---------------- scratch (device globals; no allocation allowed) ----------------
__device__ float g_h1[NN * CC];
__device__ float g_h2[NN * CC];
__device__ float g_hn[NN * CC];
__device__ float g_hw[NN * CC];
__device__ int   g_deg[NN];
__device__ int   g_off[NN + 1];
__device__ int   g_cursor[NN];
__device__ int   g_slot[EE];     // src node id per CSR slot (sorted by dst)
__device__ float g_sea0[NN];
__device__ float g_sea1[NN];
__device__ float g_inv[NN];

// ---------------- setup kernels ----------------
__global__ void k_zero() {
    int i = blockIdx.x * blockDim.x + threadIdx.x;
    if (i < NN) { g_deg[i] = 0; g_cursor[i] = 0; g_sea0[i] = 0.f; g_sea1[i] = 0.f; }
}

__global__ void k_count(const int* __restrict__ ei) {
    int e = blockIdx.x * blockDim.x + threadIdx.x;
    if (e < EE) atomicAdd(&g_deg[ei[EE + e]], 1);
}

__global__ void k_scan() {
    __shared__ int sh[1024];
    __shared__ int s_carry;
    int tid = threadIdx.x;
    if (tid == 0) s_carry = 0;
    __syncthreads();
    for (int base = 0; base < NN; base += 1024) {
        int carry = s_carry;
        int i = base + tid;
        int v = (i < NN) ? g_deg[i] : 0;
        int sum = v;
        sh[tid] = v;
        __syncthreads();
        #pragma unroll
        for (int s = 1; s < 1024; s <<= 1) {
            int t = (tid >= s) ? sh[tid - s] : 0;
            __syncthreads();
            sum += t;
            sh[tid] = sum;
            __syncthreads();
        }
        if (i < NN) g_off[i] = carry + sum - v;   // exclusive
        __syncthreads();
        if (tid == 1023) s_carry = carry + sh[1023];
        __syncthreads();
    }
    if (tid == 0) g_off[NN] = s_carry;
}

__global__ void k_scatter(const int* __restrict__ ei, const float* __restrict__ ea) {
    int e = blockIdx.x * blockDim.x + threadIdx.x;
    if (e < EE) {
        int src = ei[e];
        int dst = ei[EE + e];
        int pos = g_off[dst] + atomicAdd(&g_cursor[dst], 1);
        g_slot[pos] = src;
        atomicAdd(&g_sea0[dst], ea[2 * e]);
        atomicAdd(&g_sea1[dst], ea[2 * e + 1]);
    }
}

__global__ void k_inv() {
    int i = blockIdx.x * blockDim.x + threadIdx.x;
    if (i < NN) {
        int d = g_deg[i];
        g_inv[i] = (d > 0) ? 1.0f / (float)d : 0.0f;
    }
}

// ---------------- fp32 tiled GEMM: out[M,256] = A[M,256] @ B[256,256] ----------------
// BM=64 BN=64 BK=16, 256 threads, 4x4 microtile per thread.
__global__ __launch_bounds__(256) void k_gemm(const float* __restrict__ A,
                                              const float* __restrict__ B,
                                              float* __restrict__ out) {
    __shared__ float As[16][64];
    __shared__ float Bs[16][64];
    int tid = threadIdx.x;
    int m0 = blockIdx.x * 64;
    int n0 = blockIdx.y * 64;

    // load indices
    int ar  = tid >> 2;        // 0..63 (A tile row)
    int ac4 = tid & 3;         // 0..3  (A tile col group of 4)
    int br  = tid >> 4;        // 0..15 (B tile row)
    int bc4 = tid & 15;        // 0..15 (B tile col group of 4)

    int ty = tid >> 4;         // 0..15
    int tx = tid & 15;         // 0..15

    float acc[4][4];
    #pragma unroll
    for (int i = 0; i < 4; i++)
        #pragma unroll
        for (int j = 0; j < 4; j++) acc[i][j] = 0.f;

    for (int k0 = 0; k0 < CC; k0 += 16) {
        // A tile: rows m0..m0+63, cols k0..k0+15 -> As[k][m] (transposed)
        float4 av = make_float4(0.f, 0.f, 0.f, 0.f);
        if (m0 + ar < NN)
            av = *reinterpret_cast<const float4*>(&A[(m0 + ar) * CC + k0 + ac4 * 4]);
        As[ac4 * 4 + 0][ar] = av.x;
        As[ac4 * 4 + 1][ar] = av.y;
        As[ac4 * 4 + 2][ar] = av.z;
        As[ac4 * 4 + 3][ar] = av.w;
        // B tile: rows k0..k0+15, cols n0..n0+63
        float4 bv = *reinterpret_cast<const float4*>(&B[(k0 + br) * CC + n0 + bc4 * 4]);
        *reinterpret_cast<float4*>(&Bs[br][bc4 * 4]) = bv;
        __syncthreads();

        #pragma unroll
        for (int k = 0; k < 16; k++) {
            float a[4], b[4];
            #pragma unroll
            for (int i = 0; i < 4; i++) a[i] = As[k][ty * 4 + i];
            #pragma unroll
            for (int j = 0; j < 4; j++) b[j] = Bs[k][tx * 4 + j];
            #pragma unroll
            for (int i = 0; i < 4; i++)
                #pragma unroll
                for (int j = 0; j < 4; j++) acc[i][j] += a[i] * b[j];
        }
        __syncthreads();
    }

    #pragma unroll
    for (int i = 0; i < 4; i++) {
        int row = m0 + ty * 4 + i;
        if (row < NN) {
            float4 v = make_float4(acc[i][0], acc[i][1], acc[i][2], acc[i][3]);
            *reinterpret_cast<float4*>(&out[row * CC + n0 + tx * 4]) = v;
        }
    }
}

// ---------------- aggregation + KAF epilogue ----------------
// one block (256 threads) per node; thread c handles channel c
__global__ __launch_bounds__(256) void k_aggr_kaf(const float* __restrict__ ew,     // [2, C]
                                                  const float* __restrict__ bias,   // [C]
                                                  const float* __restrict__ alpha,  // [C, D]
                                                  float* __restrict__ h_out) {
    __shared__ int ssrc[256];
    int n = blockIdx.x;
    int c = threadIdx.x;
    int o0 = g_off[n];
    int deg = g_off[n + 1] - o0;

    float acc = 0.f;
    for (int base = 0; base < deg; base += 256) {
        int m = deg - base;
        if (m > 256) m = 256;
        if (c < m) ssrc[c] = g_slot[o0 + base + c];
        __syncthreads();
        for (int e = 0; e < m; e++)
            acc += g_hn[ssrc[e] * CC + c];
        __syncthreads();
    }

    float inv = g_inv[n];
    float s = acc * inv
            + (g_sea0[n] * ew[c] + g_sea1[n] * ew[CC + c]) * inv
            + g_hw[n * CC + c] + bias[c];

    float r = 0.f;
    #pragma unroll
    for (int d = 0; d < DD; d++) {
        float t = s - (-4.0f + (float)d * DICT_STEP);
        r += alpha[c * DD + d] * __expf(-GAMMA * t * t);
    }
    h_out[n * CC + c] = r;
}

// ---------------- launch ----------------
extern "C" void kernel_launch(void* const* d_in, const int* in_sizes, int n_in,
                              void* d_out, int out_size) {
    const float* x       = (const float*)d_in[0];
    const int*   ei      = (const int*)d_in[1];
    const float* ea      = (const float*)d_in[2];
    const float* node_w  = (const float*)d_in[3];
    const float* edge_w  = (const float*)d_in[4];
    const float* neigh_w = (const float*)d_in[5];
    const float* bias    = (const float*)d_in[6];
    const float* alpha   = (const float*)d_in[7];
    float* out = (float*)d_out;

    float *p_h1, *p_h2, *p_hn, *p_hw;
    cudaGetSymbolAddress((void**)&p_h1, g_h1);
    cudaGetSymbolAddress((void**)&p_h2, g_h2);
    cudaGetSymbolAddress((void**)&p_hn, g_hn);
    cudaGetSymbolAddress((void**)&p_hw, g_hw);

    // graph setup (once per launch; graph is fixed per input set)
    k_zero<<<(NN + 255) / 256, 256>>>();
    k_count<<<(EE + 255) / 256, 256>>>(ei);
    k_scan<<<1, 1024>>>();
    k_scatter<<<(EE + 255) / 256, 256>>>(ei, ea);
    k_inv<<<(NN + 255) / 256, 256>>>();

    dim3 gg((NN + 63) / 64, CC / 64);
    for (int l = 0; l < LL; l++) {
        const float* h_in = (l == 0) ? x : ((l == 1) ? p_h1 : p_h2);
        float* h_out      = (l == 2) ? out : ((l == 0) ? p_h1 : p_h2);
        k_gemm<<<gg, 256>>>(h_in, neigh_w + l * CC * CC, p_hn);
        k_gemm<<<gg, 256>>>(h_in, node_w + l * CC * CC, p_hw);
        k_aggr_kaf<<<NN, 256>>>(edge_w + l * 2 * CC, bias + l * CC,
                                alpha + l * CC * DD, h_out);
    }
}

// round 3
// speedup vs baseline: 1.3757x; 1.3757x over previous
#include <cuda_runtime.h>
#include <cuda_bf16.h>
#include <cstdint>

#define NN 10000
#define MPAD 10112        // 79 * 128
#define NT 79             // M tiles
#define EE 320000
#define CC 256
#define LL 3
#define DD 20
#define GAMMA 0.705078125f   // 0.5/(2*interval)^2, interval = 8/19
#define DICT_STEP (8.0f/19.0f)

// ---------------- scratch (device globals) ----------------
__device__ float g_h1[NN * CC];
__device__ float g_h2[NN * CC];
__device__ float g_hn[NN * CC];
__device__ float g_hw[NN * CC];
__device__ int   g_deg[NN];
__device__ int   g_off[NN + 1];
__device__ int   g_cursor[NN];
__device__ int   g_slot[EE];
__device__ float g_sea0[NN];
__device__ float g_sea1[NN];
__device__ float g_inv[NN];
__device__ __align__(16) __nv_bfloat16 gA_hi[MPAD * CC];
__device__ __align__(16) __nv_bfloat16 gA_lo[MPAD * CC];
__device__ __align__(16) __nv_bfloat16 gB_hi[512 * CC];   // [n][k] (k contig): n<256 neigh_w, else node_w
__device__ __align__(16) __nv_bfloat16 gB_lo[512 * CC];

// ---------------- setup kernels ----------------
__global__ void k_zero() {
    int i = blockIdx.x * blockDim.x + threadIdx.x;
    if (i < NN) { g_deg[i] = 0; g_cursor[i] = 0; g_sea0[i] = 0.f; g_sea1[i] = 0.f; }
}

__global__ void k_count(const int* __restrict__ ei) {
    int e = blockIdx.x * blockDim.x + threadIdx.x;
    if (e < EE) atomicAdd(&g_deg[ei[EE + e]], 1);
}

__global__ void k_scan() {
    __shared__ int sh[1024];
    __shared__ int s_carry;
    int tid = threadIdx.x;
    if (tid == 0) s_carry = 0;
    __syncthreads();
    for (int base = 0; base < NN; base += 1024) {
        int carry = s_carry;
        int i = base + tid;
        int v = (i < NN) ? g_deg[i] : 0;
        int sum = v;
        sh[tid] = v;
        __syncthreads();
        #pragma unroll
        for (int s = 1; s < 1024; s <<= 1) {
            int t = (tid >= s) ? sh[tid - s] : 0;
            __syncthreads();
            sum += t;
            sh[tid] = sum;
            __syncthreads();
        }
        if (i < NN) g_off[i] = carry + sum - v;
        __syncthreads();
        if (tid == 1023) s_carry = carry + sh[1023];
        __syncthreads();
    }
    if (tid == 0) g_off[NN] = s_carry;
}

__global__ void k_scatter(const int* __restrict__ ei, const float* __restrict__ ea) {
    int e = blockIdx.x * blockDim.x + threadIdx.x;
    if (e < EE) {
        int src = ei[e];
        int dst = ei[EE + e];
        int pos = g_off[dst] + atomicAdd(&g_cursor[dst], 1);
        g_slot[pos] = src;
        atomicAdd(&g_sea0[dst], ea[2 * e]);
        atomicAdd(&g_sea1[dst], ea[2 * e + 1]);
    }
}

__global__ void k_inv() {
    int i = blockIdx.x * blockDim.x + threadIdx.x;
    if (i < NN) {
        int d = g_deg[i];
        g_inv[i] = (d > 0) ? 1.0f / (float)d : 0.0f;
    }
}

// ---------------- bf16 hi/lo split ----------------
__global__ void k_split_h(const float* __restrict__ h) {
    int i = blockIdx.x * blockDim.x + threadIdx.x;
    if (i < MPAD * CC) {
        float v = (i < NN * CC) ? h[i] : 0.0f;
        __nv_bfloat16 hi = __float2bfloat16_rn(v);
        __nv_bfloat16 lo = __float2bfloat16_rn(v - __bfloat162float(hi));
        gA_hi[i] = hi;
        gA_lo[i] = lo;
    }
}

__global__ void k_prep_B(const float* __restrict__ nw, const float* __restrict__ ow) {
    int i = blockIdx.x * blockDim.x + threadIdx.x;
    if (i < 512 * CC) {
        int n = i >> 8, k = i & 255;
        float v = (n < CC) ? nw[k * CC + n] : ow[k * CC + (n - CC)];
        __nv_bfloat16 hi = __float2bfloat16_rn(v);
        __nv_bfloat16 lo = __float2bfloat16_rn(v - __bfloat162float(hi));
        gB_hi[i] = hi;
        gB_lo[i] = lo;
    }
}

// ---------------- HMMA GEMM ----------------
#define SW128(x) ((x) ^ (((x) >> 3) & 0x70))

__device__ __forceinline__ uint32_t s2u(const void* p) {
    uint32_t a;
    asm("{ .reg .u64 t; cvta.to.shared.u64 t, %1; cvt.u32.u64 %0, t; }" : "=r"(a) : "l"(p));
    return a;
}

__device__ __forceinline__ void ldsm_x4(uint32_t& r0, uint32_t& r1, uint32_t& r2, uint32_t& r3,
                                        uint32_t addr) {
    asm volatile("ldmatrix.sync.aligned.m8n8.x4.shared.b16 {%0,%1,%2,%3}, [%4];"
                 : "=r"(r0), "=r"(r1), "=r"(r2), "=r"(r3) : "r"(addr));
}

__device__ __forceinline__ void mma16816(float* c, const uint32_t* a, const uint32_t* b) {
    asm volatile(
        "mma.sync.aligned.m16n8k16.row.col.f32.bf16.bf16.f32 "
        "{%0,%1,%2,%3}, {%4,%5,%6,%7}, {%8,%9}, {%0,%1,%2,%3};"
        : "+f"(c[0]), "+f"(c[1]), "+f"(c[2]), "+f"(c[3])
        : "r"(a[0]), "r"(a[1]), "r"(a[2]), "r"(a[3]), "r"(b[0]), "r"(b[1]));
}

// SMEM: 4 buffers of [128 rows][64 bf16] (128B/row), SW128 swizzled
#define TB 16384
#define SMEM_TOTAL (4 * TB)

// grid (79, 4): block (bx,by) computes out[bx*128 .. +128, by*128 .. +128] of [MPAD, 512]
__global__ __launch_bounds__(256) void k_gemm_tc(float* __restrict__ hn, float* __restrict__ hw) {
    extern __shared__ char smem[];
    char* sAhi = smem;
    char* sAlo = smem + TB;
    char* sBhi = smem + 2 * TB;
    char* sBlo = smem + 3 * TB;
    uint32_t ubase = s2u(smem);

    int tid = threadIdx.x, wid = tid >> 5, lid = tid & 31;
    int m0 = blockIdx.x * 128;
    int nblk = blockIdx.y;            // 0..3; global col = nblk*128 + ...
    int warp_m = (wid & 3) * 32;      // row offset within CTA tile
    int warp_n = (wid >> 2) * 64;     // col offset within CTA tile

    float acc[2][8][4];
    #pragma unroll
    for (int t = 0; t < 2; t++)
        #pragma unroll
        for (int n = 0; n < 8; n++)
            #pragma unroll
            for (int j = 0; j < 4; j++) acc[t][n][j] = 0.f;

    int g = lid >> 3, rid = lid & 7;  // ldmatrix group / row-in-group

    for (int ch = 0; ch < 4; ch++) {
        int kg = ch * 64;
        // load tiles: A rows m0.., B rows nblk*128.. ; 64 k-cols each
        #pragma unroll
        for (int it = 0; it < 4; it++) {
            int i = tid + it * 256;          // 0..1023
            int r = i >> 3, c = i & 7;
            uint32_t so = SW128((uint32_t)(r * 128 + c * 16));
            int ga = (m0 + r) * CC + kg + c * 8;
            int gb = (nblk * 128 + r) * CC + kg + c * 8;
            *(uint4*)(sAhi + so) = *(const uint4*)&gA_hi[ga];
            *(uint4*)(sAlo + so) = *(const uint4*)&gA_lo[ga];
            *(uint4*)(sBhi + so) = *(const uint4*)&gB_hi[gb];
            *(uint4*)(sBlo + so) = *(const uint4*)&gB_lo[gb];
        }
        __syncthreads();

        #pragma unroll
        for (int pass = 0; pass < 3; pass++) {
            uint32_t ua = ubase + ((pass == 2) ? TB : 0);          // A_lo on pass2 else A_hi
            uint32_t ub = ubase + ((pass == 1) ? 3 * TB : 2 * TB); // B_lo on pass1 else B_hi
            #pragma unroll
            for (int ks = 0; ks < 4; ks++) {
                int kc2 = ks * 2;  // 16B-chunk index of this k-step
                // A fragments: 2 m-tiles of 16
                uint32_t a[2][4];
                #pragma unroll
                for (int t = 0; t < 2; t++) {
                    int row = warp_m + t * 16 + ((g & 1) ? 8 : 0) + rid;
                    int chunk = kc2 + (g >> 1);
                    ldsm_x4(a[t][0], a[t][1], a[t][2], a[t][3],
                            ua + SW128((uint32_t)(row * 128 + chunk * 16)));
                }
                // B fragments: 8 n-tiles of 8, loaded as 4 x4-ldmatrix (2 tiles each)
                uint32_t b[8][2];
                #pragma unroll
                for (int p = 0; p < 4; p++) {
                    int row = warp_n + p * 16 + ((g >> 1) ? 8 : 0) + rid;
                    int chunk = kc2 + (g & 1);
                    ldsm_x4(b[2 * p][0], b[2 * p][1], b[2 * p + 1][0], b[2 * p + 1][1],
                            ub + SW128((uint32_t)(row * 128 + chunk * 16)));
                }
                #pragma unroll
                for (int t = 0; t < 2; t++)
                    #pragma unroll
                    for (int n = 0; n < 8; n++)
                        mma16816(acc[t][n], a[t], b[n]);
            }
        }
        __syncthreads();
    }

    // epilogue: write fp32
    int qm = lid >> 2, qn = (lid & 3) * 2;
    #pragma unroll
    for (int t = 0; t < 2; t++) {
        #pragma unroll
        for (int n = 0; n < 8; n++) {
            int row0 = m0 + warp_m + t * 16 + qm;
            int colg = nblk * 128 + warp_n + n * 8 + qn;    // 0..511
            float* base = (colg < 256) ? hn : hw;
            int col = colg & 255;
            if (row0 < NN)
                *(float2*)&base[row0 * CC + col] = make_float2(acc[t][n][0], acc[t][n][1]);
            if (row0 + 8 < NN)
                *(float2*)&base[(row0 + 8) * CC + col] = make_float2(acc[t][n][2], acc[t][n][3]);
        }
    }
}

// ---------------- aggregation + KAF epilogue ----------------
__global__ __launch_bounds__(256) void k_aggr_kaf(const float* __restrict__ ew,
                                                  const float* __restrict__ bias,
                                                  const float* __restrict__ alpha,
                                                  float* __restrict__ h_out) {
    __shared__ int ssrc[256];
    int n = blockIdx.x;
    int c = threadIdx.x;
    int o0 = g_off[n];
    int deg = g_off[n + 1] - o0;

    float acc = 0.f;
    for (int base = 0; base < deg; base += 256) {
        int m = deg - base;
        if (m > 256) m = 256;
        if (c < m) ssrc[c] = g_slot[o0 + base + c];
        __syncthreads();
        for (int e = 0; e < m; e++)
            acc += g_hn[ssrc[e] * CC + c];
        __syncthreads();
    }

    float inv = g_inv[n];
    float s = acc * inv
            + (g_sea0[n] * ew[c] + g_sea1[n] * ew[CC + c]) * inv
            + g_hw[n * CC + c] + bias[c];

    float r = 0.f;
    #pragma unroll
    for (int d = 0; d < DD; d++) {
        float t = s - (-4.0f + (float)d * DICT_STEP);
        r += alpha[c * DD + d] * __expf(-GAMMA * t * t);
    }
    h_out[n * CC + c] = r;
}

// ---------------- launch ----------------
extern "C" void kernel_launch(void* const* d_in, const int* in_sizes, int n_in,
                              void* d_out, int out_size) {
    const float* x       = (const float*)d_in[0];
    const int*   ei      = (const int*)d_in[1];
    const float* ea      = (const float*)d_in[2];
    const float* node_w  = (const float*)d_in[3];
    const float* edge_w  = (const float*)d_in[4];
    const float* neigh_w = (const float*)d_in[5];
    const float* bias    = (const float*)d_in[6];
    const float* alpha   = (const float*)d_in[7];
    float* out = (float*)d_out;

    float *p_h1, *p_h2, *p_hn, *p_hw;
    cudaGetSymbolAddress((void**)&p_h1, g_h1);
    cudaGetSymbolAddress((void**)&p_h2, g_h2);
    cudaGetSymbolAddress((void**)&p_hn, g_hn);
    cudaGetSymbolAddress((void**)&p_hw, g_hw);

    cudaFuncSetAttribute(k_gemm_tc, cudaFuncAttributeMaxDynamicSharedMemorySize, SMEM_TOTAL);

    k_zero<<<(NN + 255) / 256, 256>>>();
    k_count<<<(EE + 255) / 256, 256>>>(ei);
    k_scan<<<1, 1024>>>();
    k_scatter<<<(EE + 255) / 256, 256>>>(ei, ea);
    k_inv<<<(NN + 255) / 256, 256>>>();

    dim3 gg(NT, 4);
    for (int l = 0; l < LL; l++) {
        const float* h_in = (l == 0) ? x : ((l == 1) ? p_h1 : p_h2);
        float* h_out      = (l == 2) ? out : ((l == 0) ? p_h1 : p_h2);
        k_split_h<<<(MPAD * CC + 255) / 256, 256>>>(h_in);
        k_prep_B<<<(512 * CC + 255) / 256, 256>>>(neigh_w + l * CC * CC, node_w + l * CC * CC);
        k_gemm_tc<<<gg, 256, SMEM_TOTAL>>>(p_hn, p_hw);
        k_aggr_kaf<<<NN, 256>>>(edge_w + l * 2 * CC, bias + l * CC,
                                alpha + l * CC * DD, h_out);
    }
}